// round 3
// baseline (speedup 1.0000x reference)
#include <cuda_runtime.h>
#include <cuda_bf16.h>
#include <cstdint>

#define BATCH 64
#define ISZ   64
#define SEQ   4096
#define ESZ   64
#define TPB   128          // threads per block
#define SPT   2            // s-values per thread (via f32x2 lanes)
#define SPB   (TPB * SPT)  // 256 s per block

// Packed fp32x2 helpers (Blackwell sm_100+)
__device__ __forceinline__ unsigned long long pk2(float a, float b) {
    unsigned long long r;
    asm("mov.b64 %0, {%1, %2};" : "=l"(r) : "f"(a), "f"(b));
    return r;
}
__device__ __forceinline__ unsigned long long fma2(unsigned long long a,
                                                   unsigned long long b,
                                                   unsigned long long c) {
    unsigned long long d;
    asm("fma.rn.f32x2 %0, %1, %2, %3;" : "=l"(d) : "l"(a), "l"(b), "l"(c));
    return d;
}
__device__ __forceinline__ void unpk2(unsigned long long v, float& lo, float& hi) {
    asm("mov.b64 {%0, %1}, %2;" : "=f"(lo), "=f"(hi) : "l"(v));
}

__global__ __launch_bounds__(TPB, 3)
void embed_f32x2_s2_kernel(const float* __restrict__ in,    // [B, I, S]
                           const float* __restrict__ emb,   // [I, E]
                           float* __restrict__ out) {       // [B, S, E]
    // Embedding duplicated into f32x2 pairs: semb2[i*64 + e] = (emb[i][e], emb[i][e])
    // so one LDS.128 (2 u64) feeds 4 FMA2 (2 e-cols x 2 s-lanes). 32 KB.
    __shared__ unsigned long long semb2[ISZ * ESZ];

    const int tid = threadIdx.x;

    // Cooperative staging: vectorized read of emb, duplicated write.
    {
        const float4* src = reinterpret_cast<const float4*>(emb);
        #pragma unroll
        for (int k = tid; k < ISZ * ESZ / 4; k += TPB) {
            float4 v = src[k];
            unsigned long long* d = &semb2[4 * k];
            d[0] = pk2(v.x, v.x);
            d[1] = pk2(v.y, v.y);
            d[2] = pk2(v.z, v.z);
            d[3] = pk2(v.w, v.w);
        }
    }
    __syncthreads();

    const int s0 = blockIdx.x * SPB + tid * SPT;   // consecutive (s0, s0+1) per thread
    const int b  = blockIdx.y;
    // x loads: 8 B per thread, warp covers 256 B contiguous -> fully coalesced.
    const unsigned long long* ip =
        reinterpret_cast<const unsigned long long*>(in + (size_t)b * ISZ * SEQ + s0);

    unsigned long long acc[ESZ];   // acc[e] = (out[s0][e], out[s1][e])  -> 128 regs
    #pragma unroll
    for (int e = 0; e < ESZ; e++) acc[e] = 0ull;

    // Contraction over i. unroll 4 keeps the body ~5 KB (I$-L0 resident) while
    // batching 4 independent LDG.64 for MLP.
    #pragma unroll 4
    for (int i = 0; i < ISZ; i++) {
        const unsigned long long xx = __ldcs(ip + (size_t)i * (SEQ / 2)); // (x[i,s0], x[i,s1])
        const ulonglong2* e2 = reinterpret_cast<const ulonglong2*>(&semb2[i * ESZ]);
        #pragma unroll
        for (int j = 0; j < ESZ / 2; j++) {       // 32 LDS.128 -> wait, 32? No: ESZ/2=32 u64 pairs
            ulonglong2 v = e2[j];                 // LDS.128 broadcast: covers e=2j, 2j+1
            acc[2 * j]     = fma2(v.x, xx, acc[2 * j]);
            acc[2 * j + 1] = fma2(v.y, xx, acc[2 * j + 1]);
        }
    }

    // Epilogue: unpack lanes and store both rows with 16 B streaming stores.
    float* op0 = out + ((size_t)b * SEQ + s0) * ESZ;   // row s0
    float* op1 = op0 + ESZ;                            // row s0+1
    #pragma unroll
    for (int j = 0; j < ESZ / 4; j++) {
        float4 v0, v1;
        unpk2(acc[4 * j + 0], v0.x, v1.x);
        unpk2(acc[4 * j + 1], v0.y, v1.y);
        unpk2(acc[4 * j + 2], v0.z, v1.z);
        unpk2(acc[4 * j + 3], v0.w, v1.w);
        __stcs(reinterpret_cast<float4*>(op0) + j, v0);
        __stcs(reinterpret_cast<float4*>(op1) + j, v1);
    }
}

extern "C" void kernel_launch(void* const* d_in, const int* in_sizes, int n_in,
                              void* d_out, int out_size) {
    const float* in  = (const float*)d_in[0];   // inputs [64, 64, 4096] fp32
    const float* emb = (const float*)d_in[1];   // embedding [64, 64] fp32
    float* out = (float*)d_out;                 // [64, 4096, 64] fp32

    dim3 grid(SEQ / SPB, BATCH);   // (16, 64) = 1024 blocks of 128 threads
    embed_f32x2_s2_kernel<<<grid, TPB>>>(in, emb, out);
}

// round 4
// speedup vs baseline: 1.4718x; 1.4718x over previous
#include <cuda_runtime.h>
#include <cuda_bf16.h>
#include <cstdint>

#define BATCH 64
#define ISZ   64
#define SEQ   4096
#define ESZ   64
#define TPB   128          // 4 warps; each warp owns a 16-e slice over 256 s
#define SPT   8            // s-values per thread
#define EPT   16           // e-values per thread (8 f32x2 pairs)
#define SPB   256          // s per block (32 lanes x 8 s, shared by all 4 warps)

// Packed fp32x2 helpers (Blackwell sm_100+)
__device__ __forceinline__ unsigned long long pk2(float a, float b) {
    unsigned long long r;
    asm("mov.b64 %0, {%1, %2};" : "=l"(r) : "f"(a), "f"(b));
    return r;
}
__device__ __forceinline__ unsigned long long fma2(unsigned long long a,
                                                   unsigned long long b,
                                                   unsigned long long c) {
    unsigned long long d;
    asm("fma.rn.f32x2 %0, %1, %2, %3;" : "=l"(d) : "l"(a), "l"(b), "l"(c));
    return d;
}
__device__ __forceinline__ void unpk2(unsigned long long v, float& lo, float& hi) {
    asm("mov.b64 {%0, %1}, %2;" : "=f"(lo), "=f"(hi) : "l"(v));
}

__global__ __launch_bounds__(TPB, 3)
void embed_rb_kernel(const float* __restrict__ in,    // [B, I, S]
                     const float* __restrict__ emb,   // [I, E]
                     float* __restrict__ out) {       // [B, S, E]
    // emb staged verbatim: adjacent e-columns form natural f32x2 pairs.
    // semb[i*32 + p] = (emb[i][2p], emb[i][2p+1]).  16 KB, no duplication.
    __shared__ unsigned long long semb[ISZ * ESZ / 2];

    const int tid  = threadIdx.x;
    const int wid  = tid >> 5;          // 0..3 -> e-slice [wid*16, wid*16+16)
    const int lane = tid & 31;

    // Cooperative 16B staging of the 64x64 embedding (straight copy).
    {
        const float4* src = reinterpret_cast<const float4*>(emb);
        float4* dst = reinterpret_cast<float4*>(semb);
        #pragma unroll
        for (int k = tid; k < ISZ * ESZ / 4; k += TPB) dst[k] = src[k];
    }
    __syncthreads();

    const int b = blockIdx.y;
    const int blk_s = blockIdx.x * SPB;
    // Thread's 8 s-values: {sA+0..3} and {sA+128..131}; per-LDG.128 the warp
    // covers a contiguous 512 B span -> 4 wavefronts each.
    const int sA = blk_s + lane * 4;
    const float* ipA = in + (size_t)b * ISZ * SEQ + sA;        // chunk A
    const float* ipB = ipA + SPB / 2;                          // chunk B (+128)

    unsigned long long acc[EPT / 2][SPT];   // acc[ep][sp] = (out[e0], out[e1]) for s=sp -> 128 regs
    #pragma unroll
    for (int ep = 0; ep < EPT / 2; ep++)
        #pragma unroll
        for (int sp = 0; sp < SPT; sp++) acc[ep][sp] = 0ull;

    const int eoff = wid * (EPT / 2);       // u64 offset of this warp's e-slice in a row

    #pragma unroll 4
    for (int i = 0; i < ISZ; i++) {
        // 16 e-values for this warp: 4 LDS.128, all lanes broadcast.
        const ulonglong2* erow =
            reinterpret_cast<const ulonglong2*>(semb + i * (ESZ / 2) + eoff);
        unsigned long long e8[EPT / 2];
        #pragma unroll
        for (int j = 0; j < EPT / 4; j++) {
            ulonglong2 v = erow[j];
            e8[2 * j]     = v.x;
            e8[2 * j + 1] = v.y;
        }
        // 8 x-values: 2 coalesced LDG.128 (re-read by 4 warps -> L1 hits).
        const float4 xa = __ldcs(reinterpret_cast<const float4*>(ipA + (size_t)i * SEQ));
        const float4 xb = __ldcs(reinterpret_cast<const float4*>(ipB + (size_t)i * SEQ));
        unsigned long long xx[SPT] = {
            pk2(xa.x, xa.x), pk2(xa.y, xa.y), pk2(xa.z, xa.z), pk2(xa.w, xa.w),
            pk2(xb.x, xb.x), pk2(xb.y, xb.y), pk2(xb.z, xb.z), pk2(xb.w, xb.w)
        };
        #pragma unroll
        for (int ep = 0; ep < EPT / 2; ep++)
            #pragma unroll
            for (int sp = 0; sp < SPT; sp++)
                acc[ep][sp] = fma2(e8[ep], xx[sp], acc[ep][sp]);
    }

    // Epilogue: each (thread, sp) owns a 64 B slice of one out row.
    #pragma unroll
    for (int sp = 0; sp < SPT; sp++) {
        const int s = (sp < 4) ? (sA + sp) : (sA + SPB / 2 + sp - 4);
        float* op = out + ((size_t)b * SEQ + s) * ESZ + wid * EPT;
        #pragma unroll
        for (int j = 0; j < EPT / 4; j++) {
            float4 v;
            unpk2(acc[2 * j][sp],     v.x, v.y);
            unpk2(acc[2 * j + 1][sp], v.z, v.w);
            __stcs(reinterpret_cast<float4*>(op) + j, v);
        }
    }
}

extern "C" void kernel_launch(void* const* d_in, const int* in_sizes, int n_in,
                              void* d_out, int out_size) {
    const float* in  = (const float*)d_in[0];   // inputs [64, 64, 4096] fp32
    const float* emb = (const float*)d_in[1];   // embedding [64, 64] fp32
    float* out = (float*)d_out;                 // [64, 4096, 64] fp32

    dim3 grid(SEQ / SPB, BATCH);   // (16, 64) = 1024 blocks of 128 threads
    embed_rb_kernel<<<grid, TPB>>>(in, emb, out);
}

// round 6
// speedup vs baseline: 2.5343x; 1.7220x over previous
#include <cuda_runtime.h>
#include <cuda_bf16.h>
#include <cstdint>

#define BATCH  64
#define ISZ    64
#define SEQ    4096
#define ESZ    64
#define TILE_M 128
#define NTILES ((BATCH * SEQ) / TILE_M)   // 2048
#define TPB    128

// SMEM layout: 128B rows, XOR-swizzled 16B chunks (chunk ^= row&7). 48 KB total.
#define SM_AHI 0          // 128 x 64 bf16 = 16 KB   A-hi [s][i]
#define SM_ALO 16384      // 16 KB                   A-lo [s][i]
#define SM_BHI 32768      //  64 x 64 bf16 =  8 KB   B-hi [i][e]
#define SM_BLO 40960      //  8 KB                   B-lo [i][e]

// Pre-split, pre-swizzled B image: [0..2047] = hi words, [2048..4095] = lo words
__device__ uint32_t g_B[4096];

__device__ __forceinline__ uint32_t smem_u32(const void* p) {
    uint32_t a;
    asm("{ .reg .u64 t; cvta.to.shared.u64 t, %1; cvt.u32.u64 %0, t; }" : "=r"(a) : "l"(p));
    return a;
}
__device__ __forceinline__ void ldsm_x4(uint32_t* r, uint32_t addr) {
    asm volatile("ldmatrix.sync.aligned.m8n8.x4.shared.b16 {%0,%1,%2,%3}, [%4];"
                 : "=r"(r[0]), "=r"(r[1]), "=r"(r[2]), "=r"(r[3]) : "r"(addr));
}
__device__ __forceinline__ void ldsm_x4_t(uint32_t* r, uint32_t addr) {
    asm volatile("ldmatrix.sync.aligned.m8n8.x4.trans.shared.b16 {%0,%1,%2,%3}, [%4];"
                 : "=r"(r[0]), "=r"(r[1]), "=r"(r[2]), "=r"(r[3]) : "r"(addr));
}
__device__ __forceinline__ void mma_bf16(float* d, const uint32_t* a, const uint32_t* b) {
    asm volatile(
        "mma.sync.aligned.m16n8k16.row.col.f32.bf16.bf16.f32 "
        "{%0,%1,%2,%3}, {%4,%5,%6,%7}, {%8,%9}, {%0,%1,%2,%3};"
        : "+f"(d[0]), "+f"(d[1]), "+f"(d[2]), "+f"(d[3])
        : "r"(a[0]), "r"(a[1]), "r"(a[2]), "r"(a[3]), "r"(b[0]), "r"(b[1]));
}
// split x into bf16 hi + bf16 lo (residual)
__device__ __forceinline__ void split2(float x0, float x1, uint32_t& hi, uint32_t& lo) {
    const __nv_bfloat16 h0 = __float2bfloat16(x0), h1 = __float2bfloat16(x1);
    const __nv_bfloat16 l0 = __float2bfloat16(x0 - __bfloat162float(h0));
    const __nv_bfloat16 l1 = __float2bfloat16(x1 - __bfloat162float(h1));
    hi = (uint32_t)__bfloat16_as_ushort(h0) | ((uint32_t)__bfloat16_as_ushort(h1) << 16);
    lo = (uint32_t)__bfloat16_as_ushort(l0) | ((uint32_t)__bfloat16_as_ushort(l1) << 16);
}

// ---------- prep: split emb [i][e] into hi/lo bf16, swizzled image in gmem ----------
__global__ void prep_B_kernel(const float* __restrict__ emb) {
    const int tid = threadIdx.x;
    for (int idx = tid; idx < 2048; idx += TPB) {
        const int k = idx >> 5;        // i row 0..63
        const int j = idx & 31;        // e-pair 0..31
        uint32_t hi, lo;
        split2(emb[k * ESZ + 2 * j], emb[k * ESZ + 2 * j + 1], hi, lo);
        const uint32_t byte = (uint32_t)(k * 128 + (((j >> 2) ^ (k & 7)) << 4) + ((j & 3) << 2));
        g_B[byte >> 2]          = hi;
        g_B[2048 + (byte >> 2)] = lo;
    }
}

// ---------- main: one 128s x 64e tile per CTA via bf16 mma.sync, 3-term split ----------
__global__ __launch_bounds__(TPB)
void embed_hmma_kernel(const float* __restrict__ in,   // [B, I, S]
                       float* __restrict__ out) {      // [B, S, E]
    __shared__ __align__(16) uint8_t smem[49152];
    const int tid = threadIdx.x, wid = tid >> 5, lane = tid & 31;
    const uint32_t sbase = smem_u32(smem);

    const int b  = blockIdx.x >> 5;
    const int s0 = (blockIdx.x & 31) << 7;

    // stage B: straight 16B copy of the pre-swizzled image (16 KB)
    {
        const float4* src = reinterpret_cast<const float4*>(g_B);
        float4* dst = reinterpret_cast<float4*>(smem + SM_BHI);
        #pragma unroll
        for (int k = tid; k < 1024; k += TPB) dst[k] = src[k];
    }

    // stage A: thread = s-row; per-i loads coalesced across threads; split + swizzled STS
    {
        const float* ap = in + (size_t)b * ISZ * SEQ + s0 + tid;
        const uint32_t rowb = (uint32_t)(tid * 128);
        const uint32_t rsw  = (uint32_t)(tid & 7);
        #pragma unroll 4
        for (int j = 0; j < 32; j++) {           // i = 2j, 2j+1
            const float x0 = __ldcs(ap + (size_t)(2 * j) * SEQ);
            const float x1 = __ldcs(ap + (size_t)(2 * j + 1) * SEQ);
            uint32_t hi, lo;
            split2(x0, x1, hi, lo);
            const uint32_t byte = rowb + ((((uint32_t)j >> 2) ^ rsw) << 4) + (((uint32_t)j & 3) << 2);
            *(uint32_t*)(smem + SM_AHI + byte) = hi;
            *(uint32_t*)(smem + SM_ALO + byte) = lo;
        }
    }
    __syncthreads();

    // ---- MMA: warp w owns rows [w*32, w*32+32) x all 64 e ----
    float acc[2][8][4];
    #pragma unroll
    for (int t = 0; t < 2; t++)
        #pragma unroll
        for (int n = 0; n < 8; n++)
            #pragma unroll
            for (int q = 0; q < 4; q++) acc[t][n][q] = 0.f;

    #pragma unroll
    for (int kk = 0; kk < 4; kk++) {             // k-step = 16
        uint32_t ahi[2][4], alo[2][4];
        #pragma unroll
        for (int t = 0; t < 2; t++) {
            const uint32_t row = (uint32_t)(wid * 32 + t * 16 + (lane & 7) + ((lane >> 3) & 1) * 8);
            const uint32_t chunk = (uint32_t)((kk * 2 + (lane >> 4)) ^ (int)(row & 7));
            const uint32_t off = row * 128 + chunk * 16;
            ldsm_x4(ahi[t], sbase + SM_AHI + off);
            ldsm_x4(alo[t], sbase + SM_ALO + off);
        }
        uint32_t bhi[8][2], blo[8][2];
        #pragma unroll
        for (int p = 0; p < 4; p++) {            // n-tile pair p -> n-tiles 2p, 2p+1
            const uint32_t krow = (uint32_t)(kk * 16 + (lane & 7) + ((lane >> 3) & 1) * 8);
            const uint32_t chunk = (uint32_t)((p * 2 + (lane >> 4)) ^ (int)(krow & 7));
            const uint32_t off = krow * 128 + chunk * 16;
            uint32_t r[4];
            ldsm_x4_t(r, sbase + SM_BHI + off);
            bhi[2 * p][0] = r[0]; bhi[2 * p][1] = r[1];
            bhi[2 * p + 1][0] = r[2]; bhi[2 * p + 1][1] = r[3];
            ldsm_x4_t(r, sbase + SM_BLO + off);
            blo[2 * p][0] = r[0]; blo[2 * p][1] = r[1];
            blo[2 * p + 1][0] = r[2]; blo[2 * p + 1][1] = r[3];
        }
        #pragma unroll
        for (int t = 0; t < 2; t++)
            #pragma unroll
            for (int n = 0; n < 8; n++) {
                mma_bf16(acc[t][n], ahi[t], bhi[n]);
                mma_bf16(acc[t][n], ahi[t], blo[n]);
                mma_bf16(acc[t][n], alo[t], bhi[n]);
            }
    }

    // ---- epilogue: fragment -> gmem, 8B stores (32B/sector coalesced per lane quad) ----
    #pragma unroll
    for (int t = 0; t < 2; t++) {
        const int sA = s0 + wid * 32 + t * 16 + (lane >> 2);
        float* opA = out + ((size_t)b * SEQ + sA) * ESZ + (lane & 3) * 2;
        float* opB = opA + 8 * ESZ;              // row +8
        #pragma unroll
        for (int n = 0; n < 8; n++) {
            float2 v0 = make_float2(acc[t][n][0], acc[t][n][1]);
            float2 v1 = make_float2(acc[t][n][2], acc[t][n][3]);
            __stcs(reinterpret_cast<float2*>(opA + n * 8), v0);
            __stcs(reinterpret_cast<float2*>(opB + n * 8), v1);
        }
    }
}

extern "C" void kernel_launch(void* const* d_in, const int* in_sizes, int n_in,
                              void* d_out, int out_size) {
    const float* in  = (const float*)d_in[0];   // inputs [64, 64, 4096] fp32
    const float* emb = (const float*)d_in[1];   // embedding [64, 64] fp32
    float* out = (float*)d_out;                 // [64, 4096, 64] fp32

    prep_B_kernel<<<1, TPB>>>(emb);
    embed_hmma_kernel<<<NTILES, TPB>>>(in, out);
}

// round 7
// speedup vs baseline: 3.6431x; 1.4375x over previous
#include <cuda_runtime.h>
#include <cuda_bf16.h>
#include <cstdint>

#define BATCH  64
#define ISZ    64
#define SEQ    4096
#define ESZ    64
#define TILE_M 64
#define NTILES ((BATCH * SEQ) / TILE_M)   // 4096
#define TPB    128

// SMEM: A tile only. 64 rows x 128 B (64 bf16), XOR-swizzled 16B chunks.
#define SM_AHI 0
#define SM_ALO 8192
#define SM_TOT 16384

// B in exact mma.sync b-fragment order:
// g_Bfrag[ ((kk*8 + nt)*2 + h)*64 + lane*2 + w ]   (4 kk x 8 nt x {hi,lo} x 32 lanes x 2 words)
__device__ uint32_t g_Bfrag[4096];   // 16 KB

__device__ __forceinline__ uint32_t smem_u32(const void* p) {
    uint32_t a;
    asm("{ .reg .u64 t; cvta.to.shared.u64 t, %1; cvt.u32.u64 %0, t; }" : "=r"(a) : "l"(p));
    return a;
}
__device__ __forceinline__ void ldsm_x4(uint32_t* r, uint32_t addr) {
    asm volatile("ldmatrix.sync.aligned.m8n8.x4.shared.b16 {%0,%1,%2,%3}, [%4];"
                 : "=r"(r[0]), "=r"(r[1]), "=r"(r[2]), "=r"(r[3]) : "r"(addr));
}
__device__ __forceinline__ void mma_bf16(float* d, const uint32_t* a, uint32_t b0, uint32_t b1) {
    asm volatile(
        "mma.sync.aligned.m16n8k16.row.col.f32.bf16.bf16.f32 "
        "{%0,%1,%2,%3}, {%4,%5,%6,%7}, {%8,%9}, {%0,%1,%2,%3};"
        : "+f"(d[0]), "+f"(d[1]), "+f"(d[2]), "+f"(d[3])
        : "r"(a[0]), "r"(a[1]), "r"(a[2]), "r"(a[3]), "r"(b0), "r"(b1));
}
__device__ __forceinline__ void split2(float x0, float x1, uint32_t& hi, uint32_t& lo) {
    const __nv_bfloat16 h0 = __float2bfloat16(x0), h1 = __float2bfloat16(x1);
    const __nv_bfloat16 l0 = __float2bfloat16(x0 - __bfloat162float(h0));
    const __nv_bfloat16 l1 = __float2bfloat16(x1 - __bfloat162float(h1));
    hi = (uint32_t)__bfloat16_as_ushort(h0) | ((uint32_t)__bfloat16_as_ushort(h1) << 16);
    lo = (uint32_t)__bfloat16_as_ushort(l0) | ((uint32_t)__bfloat16_as_ushort(l1) << 16);
}

// ---------- prep: emb -> hi/lo bf16 b-fragments in gmem ----------
__global__ void prep_B_kernel(const float* __restrict__ emb) {   // emb [i=64][e=64]
    const int tid = threadIdx.x;
    for (int idx = tid; idx < 2048; idx += TPB) {
        const int lane = idx & 31;
        const int rest = idx >> 5;       // ((kk*8+nt)*2 + h), 0..63
        const int h    = rest & 1;
        const int tile = rest >> 1;      // kk*8 + nt
        const int kk   = tile >> 3;
        const int nt   = tile & 7;
        const int n    = nt * 8 + (lane >> 2);
        #pragma unroll
        for (int w = 0; w < 2; w++) {
            const int k0 = kk * 16 + 2 * (lane & 3) + w * 8;
            uint32_t hi, lo;
            split2(emb[k0 * ESZ + n], emb[(k0 + 1) * ESZ + n], hi, lo);
            g_Bfrag[rest * 64 + lane * 2 + w] = h ? lo : hi;
        }
    }
}

// ---------- main: 64s x 64e tile per CTA; warp = 32s x 32e ----------
__global__ __launch_bounds__(TPB, 6)
void embed_hmma2_kernel(const float* __restrict__ in,   // [B, I, S]
                        float* __restrict__ out) {      // [B, S, E]
    __shared__ __align__(16) uint8_t smem[SM_TOT];
    const int tid = threadIdx.x, wid = tid >> 5, lane = tid & 31;
    const uint32_t sbase = smem_u32(smem);

    const int b  = blockIdx.x >> 6;            // 64 tiles per batch (4096/64)
    const int s0 = (blockIdx.x & 63) << 6;

    // ---- stage A: thread = (row r, i-half h); 8 i per chunk -> STS.128 x2 ----
    {
        const int r = tid & 63;
        const int h = tid >> 6;                // chunks h*4 .. h*4+3
        const float* ap = in + (size_t)b * ISZ * SEQ + (size_t)(h * 32) * SEQ + s0 + r;
        const uint32_t rsw = (uint32_t)(r & 7);
        #pragma unroll
        for (int c = 0; c < 4; c++) {
            float x[8];
            #pragma unroll
            for (int j = 0; j < 8; j++) x[j] = __ldcs(ap + (size_t)(c * 8 + j) * SEQ);
            uint32_t hi[4], lo[4];
            #pragma unroll
            for (int j = 0; j < 4; j++) split2(x[2 * j], x[2 * j + 1], hi[j], lo[j]);
            const uint32_t chunk = (uint32_t)(h * 4 + c);
            const uint32_t byte = (uint32_t)(r * 128) + ((chunk ^ rsw) << 4);
            *(uint4*)(smem + SM_AHI + byte) = make_uint4(hi[0], hi[1], hi[2], hi[3]);
            *(uint4*)(smem + SM_ALO + byte) = make_uint4(lo[0], lo[1], lo[2], lo[3]);
        }
    }
    __syncthreads();

    // ---- MMA: warp w -> rows [(w>>1)*32, +32), n-tiles [(w&1)*4, +4) ----
    const int wr = (wid >> 1) * 32;
    const int wn = (wid & 1) * 4;

    float acc[2][4][4];
    #pragma unroll
    for (int t = 0; t < 2; t++)
        #pragma unroll
        for (int n = 0; n < 4; n++)
            #pragma unroll
            for (int q = 0; q < 4; q++) acc[t][n][q] = 0.f;

    #pragma unroll
    for (int kk = 0; kk < 4; kk++) {
        uint32_t ahi[2][4], alo[2][4];
        #pragma unroll
        for (int t = 0; t < 2; t++) {
            const uint32_t row = (uint32_t)(wr + t * 16 + (lane & 7) + ((lane >> 3) & 1) * 8);
            const uint32_t chunk = (uint32_t)((kk * 2 + (lane >> 4)) ^ (int)(row & 7));
            const uint32_t off = row * 128 + chunk * 16;
            ldsm_x4(ahi[t], sbase + SM_AHI + off);
            ldsm_x4(alo[t], sbase + SM_ALO + off);
        }
        #pragma unroll
        for (int nt = 0; nt < 4; nt++) {
            const uint32_t base = (uint32_t)(((kk * 8 + (wn + nt)) * 2) * 64 + lane * 2);
            const uint2 bh = *(const uint2*)&g_Bfrag[base];        // hi frag (b0,b1)
            const uint2 bl = *(const uint2*)&g_Bfrag[base + 64];   // lo frag
            #pragma unroll
            for (int t = 0; t < 2; t++) {
                mma_bf16(acc[t][nt], ahi[t], bh.x, bh.y);
                mma_bf16(acc[t][nt], ahi[t], bl.x, bl.y);
                mma_bf16(acc[t][nt], alo[t], bh.x, bh.y);
            }
        }
    }

    // ---- epilogue: fragment -> gmem (8 B stores, quad-coalesced) ----
    #pragma unroll
    for (int t = 0; t < 2; t++) {
        const int sA = s0 + wr + t * 16 + (lane >> 2);
        float* rowA = out + ((size_t)b * SEQ + sA) * ESZ;
        float* rowB = rowA + 8 * ESZ;               // row +8
        #pragma unroll
        for (int nt = 0; nt < 4; nt++) {
            const int col = (wn + nt) * 8 + (lane & 3) * 2;
            __stcs(reinterpret_cast<float2*>(rowA + col),
                   make_float2(acc[t][nt][0], acc[t][nt][1]));
            __stcs(reinterpret_cast<float2*>(rowB + col),
                   make_float2(acc[t][nt][2], acc[t][nt][3]));
        }
    }
}

extern "C" void kernel_launch(void* const* d_in, const int* in_sizes, int n_in,
                              void* d_out, int out_size) {
    const float* in  = (const float*)d_in[0];   // inputs [64, 64, 4096] fp32
    const float* emb = (const float*)d_in[1];   // embedding [64, 64] fp32
    float* out = (float*)d_out;                 // [64, 4096, 64] fp32

    prep_B_kernel<<<1, TPB>>>(emb);
    embed_hmma2_kernel<<<NTILES, TPB>>>(in, out);
}